// round 1
// baseline (speedup 1.0000x reference)
#include <cuda_runtime.h>
#include <cuda_bf16.h>
#include <math.h>

// Problem constants (fixed by the dataset)
#define NN 50000
#define EE 400000
#define FF 128
#define HH 8
#define DD 16
#define LL 2

// ---------------- scratch (device globals; no cudaMalloc allowed) ----------
__device__ float g_h[NN * FF];            // node features [N,128]
__device__ float g_kqv[NN * 3 * FF];      // [N,384]: k|q|v
__device__ float g_krel[2 * NN * FF];     // [etype,N,128]
__device__ float g_vrel[2 * NN * FF];     // [etype,N,128]
__device__ float g_alpha[2 * EE * HH];    // per (edge,head) logits
__device__ int   g_mkey[NN * HH];         // ordered-int segment max
__device__ float g_denom[NN * HH];        // softmax denominator
__device__ float g_agg[NN * FF];          // aggregated messages / gelu buffer

// ---------------- helpers ---------------------------------------------------
__device__ __forceinline__ int f2okey(float f) {
    int i = __float_as_int(f);
    return (i >= 0) ? i : (i ^ 0x7FFFFFFF);
}
__device__ __forceinline__ float okey2f(int k) {
    int i = (k >= 0) ? k : (k ^ 0x7FFFFFFF);
    return __int_as_float(i);
}

// ---------------- GEMM: C[M,Nc] = A[M,K] @ B[K,Nc] (+bias, optional skip) --
// BM=64, BN=64, BK=16, 256 threads, 4x4 micro-tile.
// EPI=0: C = A@B + bias
// EPI=1: h = relu(g*(A@B+bias) + (1-g)*h),  g = sigmoid(*skip_p)  (writes hio)
template <int EPI>
__global__ void gemm_kernel(const float* __restrict__ A,
                            const float* __restrict__ B,
                            const float* __restrict__ bias,
                            float* __restrict__ C,
                            int M, int Nc, int K,
                            float* __restrict__ hio,
                            const float* __restrict__ skip_p) {
    __shared__ float As[64][16];
    __shared__ float Bs[16][64];
    const int tid = threadIdx.x;
    const int tx = tid & 15;
    const int ty = tid >> 4;
    const int rowBase = blockIdx.x * 64;
    const int colBase = blockIdx.y * 64;

    float acc[4][4] = {};

    for (int k0 = 0; k0 < K; k0 += 16) {
#pragma unroll
        for (int i = 0; i < 4; i++) {
            int idx = tid + i * 256;
            int r = idx >> 4, c = idx & 15;
            int gr = rowBase + r;
            As[r][c] = (gr < M) ? A[(size_t)gr * K + k0 + c] : 0.0f;
        }
#pragma unroll
        for (int i = 0; i < 4; i++) {
            int idx = tid + i * 256;
            int r = idx >> 6, c = idx & 63;
            Bs[r][c] = B[(size_t)(k0 + r) * Nc + colBase + c];
        }
        __syncthreads();
#pragma unroll
        for (int kk = 0; kk < 16; kk++) {
            float a[4], b[4];
#pragma unroll
            for (int i = 0; i < 4; i++) a[i] = As[ty * 4 + i][kk];
#pragma unroll
            for (int j = 0; j < 4; j++) b[j] = Bs[kk][tx * 4 + j];
#pragma unroll
            for (int i = 0; i < 4; i++)
#pragma unroll
                for (int j = 0; j < 4; j++) acc[i][j] = fmaf(a[i], b[j], acc[i][j]);
        }
        __syncthreads();
    }

    float g = 0.0f;
    if (EPI == 1) g = 1.0f / (1.0f + expf(-skip_p[0]));

#pragma unroll
    for (int i = 0; i < 4; i++) {
        int row = rowBase + ty * 4 + i;
        if (row >= M) continue;
#pragma unroll
        for (int j = 0; j < 4; j++) {
            int col = colBase + tx * 4 + j;
            float c = acc[i][j] + bias[col];
            if (EPI == 0) {
                C[(size_t)row * Nc + col] = c;
            } else {
                size_t o = (size_t)row * Nc + col;
                float hold = hio[o];
                float hn = g * c + (1.0f - g) * hold;
                hio[o] = fmaxf(hn, 0.0f);
            }
        }
    }
}

// ---------------- relation transform: k_rel/v_rel per edge type -------------
// k_rel[e,n,h,f] = sum_d k[n,h,d] * krel_w[e,h,d,f]  (same for v)
__global__ void rel_kernel(const float* __restrict__ kqv,
                           const float* __restrict__ krel_w_l,   // [2,8,16,16]
                           const float* __restrict__ vrel_w_l,
                           float* __restrict__ k_rel,
                           float* __restrict__ v_rel,
                           int Ntot) {
    __shared__ float wk[4096];
    __shared__ float wv[4096];
    __shared__ float sk[128];
    __shared__ float sv[128];
    const int tid = threadIdx.x;  // 128
    for (int i = tid; i < 4096; i += 128) {
        wk[i] = krel_w_l[i];
        wv[i] = vrel_w_l[i];
    }
    __syncthreads();
    const int h = tid >> 4;
    const int f = tid & 15;
    const int base = blockIdx.x * 16;
    for (int nn = 0; nn < 16; nn++) {
        int n = base + nn;
        if (n >= Ntot) break;  // uniform across block
        sk[tid] = kqv[(size_t)n * 384 + tid];
        sv[tid] = kqv[(size_t)n * 384 + 256 + tid];
        __syncthreads();
        float a0 = 0.f, a1 = 0.f, b0 = 0.f, b1 = 0.f;
#pragma unroll
        for (int d = 0; d < 16; d++) {
            float kk = sk[h * 16 + d];
            float vv = sv[h * 16 + d];
            a0 = fmaf(kk, wk[(0 * 8 + h) * 256 + d * 16 + f], a0);
            a1 = fmaf(kk, wk[(1 * 8 + h) * 256 + d * 16 + f], a1);
            b0 = fmaf(vv, wv[(0 * 8 + h) * 256 + d * 16 + f], b0);
            b1 = fmaf(vv, wv[(1 * 8 + h) * 256 + d * 16 + f], b1);
        }
        k_rel[(size_t)n * 128 + tid] = a0;
        k_rel[(size_t)Ntot * 128 + (size_t)n * 128 + tid] = a1;
        v_rel[(size_t)n * 128 + tid] = b0;
        v_rel[(size_t)Ntot * 128 + (size_t)n * 128 + tid] = b1;
        __syncthreads();
    }
}

// ---------------- per-layer init --------------------------------------------
__global__ void init_seg_kernel(float* __restrict__ agg, float* __restrict__ denom,
                                int* __restrict__ mkey, int n) {
    int t = blockIdx.x * blockDim.x + threadIdx.x;
    if (t < n * 128) agg[t] = 0.0f;
    if (t < n * 8) {
        denom[t] = 0.0f;
        mkey[t] = (int)0x80000000;
    }
}

// ---------------- edge pass 1: logits + segment max --------------------------
__global__ void edge_alpha_kernel(const int* __restrict__ ef, const int* __restrict__ er,
                                  int Ef, int Er,
                                  const float* __restrict__ kqv,
                                  const float* __restrict__ k_rel,
                                  const float* __restrict__ p_rel_l,  // [2,8]
                                  float* __restrict__ alpha,
                                  int* __restrict__ mkey, int Ntot) {
    int t = blockIdx.x * blockDim.x + threadIdx.x;
    int tot = (Ef + Er) * 8;
    if (t >= tot) return;
    int h = t & 7;
    int e = t >> 3;
    int src, dst, et;
    if (e < Ef) { et = 0; src = ef[e]; dst = ef[Ef + e]; }
    else        { int e2 = e - Ef; et = 1; src = er[e2]; dst = er[Er + e2]; }

    const float4* qp = (const float4*)(kqv + (size_t)dst * 384 + 128 + h * 16);
    const float4* kp = (const float4*)(k_rel + ((size_t)et * Ntot + src) * 128 + h * 16);
    float s = 0.f;
#pragma unroll
    for (int i = 0; i < 4; i++) {
        float4 a = qp[i], b = kp[i];
        s += a.x * b.x + a.y * b.y + a.z * b.z + a.w * b.w;
    }
    s *= p_rel_l[et * 8 + h] * 0.25f;  // scale = 1/sqrt(16)
    alpha[(size_t)e * 8 + h] = s;
    atomicMax(mkey + (size_t)dst * 8 + h, f2okey(s));
}

// ---------------- edge pass 2: exp, denom, weighted V aggregation -----------
__global__ void edge_agg_kernel(const int* __restrict__ ef, const int* __restrict__ er,
                                int Ef, int Er,
                                const float* __restrict__ v_rel,
                                const float* __restrict__ alpha,
                                const int* __restrict__ mkey,
                                float* __restrict__ denom,
                                float* __restrict__ agg, int Ntot) {
    int t = blockIdx.x * blockDim.x + threadIdx.x;
    int tot = (Ef + Er) * 8;
    if (t >= tot) return;
    int h = t & 7;
    int e = t >> 3;
    int src, dst, et;
    if (e < Ef) { et = 0; src = ef[e]; dst = ef[Ef + e]; }
    else        { int e2 = e - Ef; et = 1; src = er[e2]; dst = er[Er + e2]; }

    float m = okey2f(mkey[(size_t)dst * 8 + h]);
    float ex = expf(alpha[(size_t)e * 8 + h] - m);
    atomicAdd(denom + (size_t)dst * 8 + h, ex);

    const float4* vp = (const float4*)(v_rel + ((size_t)et * Ntot + src) * 128 + h * 16);
    float* ag = agg + (size_t)dst * 128 + h * 16;
#pragma unroll
    for (int i = 0; i < 4; i++) {
        float4 v = vp[i];
        atomicAdd(ag + i * 4 + 0, ex * v.x);
        atomicAdd(ag + i * 4 + 1, ex * v.y);
        atomicAdd(ag + i * 4 + 2, ex * v.z);
        atomicAdd(ag + i * 4 + 3, ex * v.w);
    }
}

// ---------------- normalize + exact GELU -------------------------------------
__global__ void finalize_kernel(float* __restrict__ agg, const float* __restrict__ denom,
                                int n) {
    int t = blockIdx.x * blockDim.x + threadIdx.x;
    if (t >= n * 128) return;
    int node = t >> 7;
    int h = (t >> 4) & 7;
    float v = agg[t] / (denom[node * 8 + h] + 1e-16f);
    agg[t] = 0.5f * v * (1.0f + erff(v * 0.70710678118654752440f));
}

// ---------------- head: logits [N,2] -----------------------------------------
__global__ void head_kernel(const float* __restrict__ h, const float* __restrict__ w,
                            const float* __restrict__ b, float* __restrict__ out, int n) {
    int gw = (blockIdx.x * blockDim.x + threadIdx.x) >> 5;
    int lane = threadIdx.x & 31;
    if (gw >= n) return;
    const float* hr = h + (size_t)gw * 128;
    float s0 = 0.f, s1 = 0.f;
#pragma unroll
    for (int k = lane; k < 128; k += 32) {
        float hv = hr[k];
        s0 = fmaf(hv, w[k * 2 + 0], s0);
        s1 = fmaf(hv, w[k * 2 + 1], s1);
    }
#pragma unroll
    for (int o = 16; o > 0; o >>= 1) {
        s0 += __shfl_down_sync(0xFFFFFFFFu, s0, o);
        s1 += __shfl_down_sync(0xFFFFFFFFu, s1, o);
    }
    if (lane == 0) {
        out[(size_t)gw * 2 + 0] = s0 + b[0];
        out[(size_t)gw * 2 + 1] = s1 + b[1];
    }
}

// ---------------- launch ------------------------------------------------------
extern "C" void kernel_launch(void* const* d_in, const int* in_sizes, int n_in,
                              void* d_out, int out_size) {
    const float* x       = (const float*)d_in[0];
    const int*   ef      = (const int*)d_in[1];
    const int*   er      = (const int*)d_in[2];
    const float* in_w    = (const float*)d_in[3];
    const float* in_b    = (const float*)d_in[4];
    const float* kqv_w   = (const float*)d_in[5];
    const float* kqv_b   = (const float*)d_in[6];
    const float* krel_w  = (const float*)d_in[7];
    const float* vrel_w  = (const float*)d_in[8];
    const float* p_rel   = (const float*)d_in[9];
    const float* out_w   = (const float*)d_in[10];
    const float* out_b   = (const float*)d_in[11];
    const float* skip    = (const float*)d_in[12];
    const float* head_w  = (const float*)d_in[13];
    const float* head_b  = (const float*)d_in[14];
    float* out = (float*)d_out;

    const int N  = in_sizes[0] / FF;
    const int Ef = in_sizes[1] / 2;
    const int Er = in_sizes[2] / 2;
    const int Etot = Ef + Er;

    float* hbuf;   cudaGetSymbolAddress((void**)&hbuf, g_h);
    float* kqv;    cudaGetSymbolAddress((void**)&kqv, g_kqv);
    float* krel;   cudaGetSymbolAddress((void**)&krel, g_krel);
    float* vrel;   cudaGetSymbolAddress((void**)&vrel, g_vrel);
    float* alpha;  cudaGetSymbolAddress((void**)&alpha, g_alpha);
    int*   mkey;   cudaGetSymbolAddress((void**)&mkey, g_mkey);
    float* denom;  cudaGetSymbolAddress((void**)&denom, g_denom);
    float* agg;    cudaGetSymbolAddress((void**)&agg, g_agg);

    const int gmRows = (N + 63) / 64;

    // h = x @ in_w + in_b
    gemm_kernel<0><<<dim3(gmRows, FF / 64), 256>>>(x, in_w, in_b, hbuf, N, FF, FF,
                                                   nullptr, nullptr);

    for (int l = 0; l < LL; l++) {
        // kqv = h @ kqv_w[l] + kqv_b[l]
        gemm_kernel<0><<<dim3(gmRows, (3 * FF) / 64), 256>>>(
            hbuf, kqv_w + (size_t)l * FF * 3 * FF, kqv_b + (size_t)l * 3 * FF,
            kqv, N, 3 * FF, FF, nullptr, nullptr);

        // relation transforms
        rel_kernel<<<(N + 15) / 16, 128>>>(kqv,
                                           krel_w + (size_t)l * 2 * HH * DD * DD,
                                           vrel_w + (size_t)l * 2 * HH * DD * DD,
                                           krel, vrel, N);

        // reset segment buffers
        init_seg_kernel<<<(N * 128 + 255) / 256, 256>>>(agg, denom, mkey, N);

        // edge pass 1: logits + segment max
        edge_alpha_kernel<<<(Etot * 8 + 255) / 256, 256>>>(
            ef, er, Ef, Er, kqv, krel, p_rel + (size_t)l * 2 * HH, alpha, mkey, N);

        // edge pass 2: exp / denom / weighted aggregation
        edge_agg_kernel<<<(Etot * 8 + 255) / 256, 256>>>(
            ef, er, Ef, Er, vrel, alpha, mkey, denom, agg, N);

        // normalize + gelu
        finalize_kernel<<<(N * 128 + 255) / 256, 256>>>(agg, denom, N);

        // h = relu(g * (gelu_agg @ out_w[l] + out_b[l]) + (1-g) * h)
        gemm_kernel<1><<<dim3(gmRows, FF / 64), 256>>>(
            agg, out_w + (size_t)l * FF * FF, out_b + (size_t)l * FF,
            nullptr, N, FF, FF, hbuf, skip + l);
    }

    // logits
    head_kernel<<<(N * 32 + 255) / 256, 256>>>(hbuf, head_w, head_b, out, N);
}

// round 2
// speedup vs baseline: 1.0577x; 1.0577x over previous
#include <cuda_runtime.h>
#include <cuda_bf16.h>
#include <math.h>

// Problem constants (fixed by the dataset)
#define NN 50000
#define EE 400000
#define FF 128
#define HH 8
#define DD 16
#define LL 2

// ---------------- scratch (device globals; no cudaMalloc allowed) ----------
__device__ float g_h[NN * FF];            // node features [N,128]
__device__ float g_kqv[NN * 3 * FF];      // [N,384]: k|q|v
__device__ float g_krel[2 * NN * FF];     // [etype,N,128]
__device__ float g_vrel[2 * NN * FF];     // [etype,N,128]
__device__ float g_alpha[2 * EE * HH];    // per (edge,head) logits
__device__ int   g_mkey[NN * HH];         // ordered-int segment max
__device__ float g_denom[NN * HH];        // softmax denominator
__device__ float g_agg[NN * FF];          // aggregated messages / gelu buffer

// ---------------- helpers ---------------------------------------------------
__device__ __forceinline__ int f2okey(float f) {
    int i = __float_as_int(f);
    return (i >= 0) ? i : (i ^ 0x7FFFFFFF);
}
__device__ __forceinline__ float okey2f(int k) {
    int i = (k >= 0) ? k : (k ^ 0x7FFFFFFF);
    return __int_as_float(i);
}

// ================= GEMM: C[M,Nc] = A[M,K] @ B[K,Nc] (+bias, optional skip) ==
// 128x128 tile, BK=16, 256 threads, 8x8 micro-tile, double-buffered smem,
// packed f32x2 FMA (FFMA2) in the inner loop.
// EPI=0: C = A@B + bias
// EPI=1: h = relu(g*(A@B+bias) + (1-g)*h),  g = sigmoid(*skip_p)  (writes hio)
#define ASTR 132   // padded row stride for A smem planes (16B-aligned, low-conflict)

template <int EPI>
__global__ __launch_bounds__(256, 2)
void gemm128_kernel(const float* __restrict__ A,
                    const float* __restrict__ B,
                    const float* __restrict__ bias,
                    float* __restrict__ C,
                    int M, int Nc, int K,
                    float* __restrict__ hio,
                    const float* __restrict__ skip_p) {
    __shared__ float As[2][16][ASTR];   // [buf][k][row]
    __shared__ float Bs[2][16][128];    // [buf][k][col]

    const int tid = threadIdx.x;
    const int tx = tid & 15;            // micro-tile col group
    const int ty = tid >> 4;            // micro-tile row group
    const int rowBase = blockIdx.x * 128;
    const int colBase = blockIdx.y * 128;

    // A loader mapping: 128 rows x 16 k per tile; float4 along K
    const int arow  = tid >> 2;         // 0..63 (and +64)
    const int aquad = tid & 3;          // which float4 of the 16-k slab
    // B loader mapping: 16 k rows x 128 cols; float4 along N
    const int brow = tid >> 5;          // 0..7 (and +8)
    const int bcol = (tid & 31) * 4;

    const int ntiles = K >> 4;

    // ---- preload tile 0 ----
    {
        const int gr0 = rowBase + arow;
        const int gr1 = gr0 + 64;
        float4 a0 = make_float4(0.f, 0.f, 0.f, 0.f), a1 = a0;
        if (gr0 < M) a0 = *(const float4*)(A + (size_t)gr0 * K + aquad * 4);
        if (gr1 < M) a1 = *(const float4*)(A + (size_t)gr1 * K + aquad * 4);
        As[0][aquad * 4 + 0][arow] = a0.x;  As[0][aquad * 4 + 1][arow] = a0.y;
        As[0][aquad * 4 + 2][arow] = a0.z;  As[0][aquad * 4 + 3][arow] = a0.w;
        As[0][aquad * 4 + 0][arow + 64] = a1.x;  As[0][aquad * 4 + 1][arow + 64] = a1.y;
        As[0][aquad * 4 + 2][arow + 64] = a1.z;  As[0][aquad * 4 + 3][arow + 64] = a1.w;
        float4 b0 = *(const float4*)(B + (size_t)brow * Nc + colBase + bcol);
        float4 b1 = *(const float4*)(B + (size_t)(brow + 8) * Nc + colBase + bcol);
        *(float4*)&Bs[0][brow][bcol]     = b0;
        *(float4*)&Bs[0][brow + 8][bcol] = b1;
    }
    __syncthreads();

    // packed f32x2 accumulators: 8 rows x 4 col-pairs
    unsigned long long acc[8][4];
#pragma unroll
    for (int i = 0; i < 8; i++)
#pragma unroll
        for (int j = 0; j < 4; j++) acc[i][j] = 0ULL;

    for (int kt = 0; kt < ntiles; kt++) {
        const int cur = kt & 1;
        const bool has = (kt + 1 < ntiles);
        float4 pa0, pa1, pb0, pb1;
        if (has) {
            const int k0 = (kt + 1) << 4;
            const int gr0 = rowBase + arow;
            const int gr1 = gr0 + 64;
            pa0 = make_float4(0.f, 0.f, 0.f, 0.f);
            pa1 = pa0;
            if (gr0 < M) pa0 = *(const float4*)(A + (size_t)gr0 * K + k0 + aquad * 4);
            if (gr1 < M) pa1 = *(const float4*)(A + (size_t)gr1 * K + k0 + aquad * 4);
            pb0 = *(const float4*)(B + (size_t)(k0 + brow) * Nc + colBase + bcol);
            pb1 = *(const float4*)(B + (size_t)(k0 + brow + 8) * Nc + colBase + bcol);
        }

#pragma unroll
        for (int kk = 0; kk < 16; kk++) {
            float4 av0 = *(const float4*)&As[cur][kk][ty * 8];
            float4 av1 = *(const float4*)&As[cur][kk][ty * 8 + 4];
            ulonglong2 bv0 = *(const ulonglong2*)&Bs[cur][kk][tx * 8];
            ulonglong2 bv1 = *(const ulonglong2*)&Bs[cur][kk][tx * 8 + 4];
            unsigned long long b2[4] = {bv0.x, bv0.y, bv1.x, bv1.y};
            float af[8] = {av0.x, av0.y, av0.z, av0.w, av1.x, av1.y, av1.z, av1.w};
#pragma unroll
            for (int i = 0; i < 8; i++) {
                unsigned long long a2;
                asm("mov.b64 %0, {%1, %1};" : "=l"(a2) : "f"(af[i]));
#pragma unroll
                for (int jp = 0; jp < 4; jp++) {
                    asm("fma.rn.f32x2 %0, %1, %2, %0;"
                        : "+l"(acc[i][jp]) : "l"(a2), "l"(b2[jp]));
                }
            }
        }

        if (has) {
            const int nxt = cur ^ 1;
            As[nxt][aquad * 4 + 0][arow] = pa0.x;  As[nxt][aquad * 4 + 1][arow] = pa0.y;
            As[nxt][aquad * 4 + 2][arow] = pa0.z;  As[nxt][aquad * 4 + 3][arow] = pa0.w;
            As[nxt][aquad * 4 + 0][arow + 64] = pa1.x;  As[nxt][aquad * 4 + 1][arow + 64] = pa1.y;
            As[nxt][aquad * 4 + 2][arow + 64] = pa1.z;  As[nxt][aquad * 4 + 3][arow + 64] = pa1.w;
            *(float4*)&Bs[nxt][brow][bcol]     = pb0;
            *(float4*)&Bs[nxt][brow + 8][bcol] = pb1;
            __syncthreads();
        }
    }

    // ---- epilogue ----
    float g = 0.0f;
    if (EPI == 1) g = 1.0f / (1.0f + expf(-skip_p[0]));

    float4 bb0 = *(const float4*)(bias + colBase + tx * 8);
    float4 bb1 = *(const float4*)(bias + colBase + tx * 8 + 4);

#pragma unroll
    for (int i = 0; i < 8; i++) {
        const int row = rowBase + ty * 8 + i;
        if (row >= M) continue;
        float c[8];
#pragma unroll
        for (int jp = 0; jp < 4; jp++) {
            asm("mov.b64 {%0, %1}, %2;"
                : "=f"(c[jp * 2]), "=f"(c[jp * 2 + 1]) : "l"(acc[i][jp]));
        }
        c[0] += bb0.x; c[1] += bb0.y; c[2] += bb0.z; c[3] += bb0.w;
        c[4] += bb1.x; c[5] += bb1.y; c[6] += bb1.z; c[7] += bb1.w;
        const size_t o = (size_t)row * Nc + colBase + tx * 8;
        if (EPI == 0) {
            *(float4*)(C + o)     = make_float4(c[0], c[1], c[2], c[3]);
            *(float4*)(C + o + 4) = make_float4(c[4], c[5], c[6], c[7]);
        } else {
            float4 h0 = *(const float4*)(hio + o);
            float4 h1 = *(const float4*)(hio + o + 4);
            float4 r0, r1;
            r0.x = fmaxf(g * c[0] + (1.0f - g) * h0.x, 0.0f);
            r0.y = fmaxf(g * c[1] + (1.0f - g) * h0.y, 0.0f);
            r0.z = fmaxf(g * c[2] + (1.0f - g) * h0.z, 0.0f);
            r0.w = fmaxf(g * c[3] + (1.0f - g) * h0.w, 0.0f);
            r1.x = fmaxf(g * c[4] + (1.0f - g) * h1.x, 0.0f);
            r1.y = fmaxf(g * c[5] + (1.0f - g) * h1.y, 0.0f);
            r1.z = fmaxf(g * c[6] + (1.0f - g) * h1.z, 0.0f);
            r1.w = fmaxf(g * c[7] + (1.0f - g) * h1.w, 0.0f);
            *(float4*)(hio + o)     = r0;
            *(float4*)(hio + o + 4) = r1;
        }
    }
}

// ---------------- relation transform: k_rel/v_rel per edge type -------------
__global__ void rel_kernel(const float* __restrict__ kqv,
                           const float* __restrict__ krel_w_l,   // [2,8,16,16]
                           const float* __restrict__ vrel_w_l,
                           float* __restrict__ k_rel,
                           float* __restrict__ v_rel,
                           int Ntot) {
    __shared__ float wk[4096];
    __shared__ float wv[4096];
    __shared__ float sk[128];
    __shared__ float sv[128];
    const int tid = threadIdx.x;  // 128
    for (int i = tid; i < 4096; i += 128) {
        wk[i] = krel_w_l[i];
        wv[i] = vrel_w_l[i];
    }
    __syncthreads();
    const int h = tid >> 4;
    const int f = tid & 15;
    const int base = blockIdx.x * 16;
    for (int nn = 0; nn < 16; nn++) {
        int n = base + nn;
        if (n >= Ntot) break;  // uniform across block
        sk[tid] = kqv[(size_t)n * 384 + tid];
        sv[tid] = kqv[(size_t)n * 384 + 256 + tid];
        __syncthreads();
        float a0 = 0.f, a1 = 0.f, b0 = 0.f, b1 = 0.f;
#pragma unroll
        for (int d = 0; d < 16; d++) {
            float kk = sk[h * 16 + d];
            float vv = sv[h * 16 + d];
            a0 = fmaf(kk, wk[(0 * 8 + h) * 256 + d * 16 + f], a0);
            a1 = fmaf(kk, wk[(1 * 8 + h) * 256 + d * 16 + f], a1);
            b0 = fmaf(vv, wv[(0 * 8 + h) * 256 + d * 16 + f], b0);
            b1 = fmaf(vv, wv[(1 * 8 + h) * 256 + d * 16 + f], b1);
        }
        k_rel[(size_t)n * 128 + tid] = a0;
        k_rel[(size_t)Ntot * 128 + (size_t)n * 128 + tid] = a1;
        v_rel[(size_t)n * 128 + tid] = b0;
        v_rel[(size_t)Ntot * 128 + (size_t)n * 128 + tid] = b1;
        __syncthreads();
    }
}

// ---------------- per-layer init --------------------------------------------
__global__ void init_seg_kernel(float* __restrict__ agg, float* __restrict__ denom,
                                int* __restrict__ mkey, int n) {
    int t = blockIdx.x * blockDim.x + threadIdx.x;
    if (t < n * 128) agg[t] = 0.0f;
    if (t < n * 8) {
        denom[t] = 0.0f;
        mkey[t] = (int)0x80000000;
    }
}

// ---------------- edge pass 1: logits + segment max --------------------------
__global__ void edge_alpha_kernel(const int* __restrict__ ef, const int* __restrict__ er,
                                  int Ef, int Er,
                                  const float* __restrict__ kqv,
                                  const float* __restrict__ k_rel,
                                  const float* __restrict__ p_rel_l,  // [2,8]
                                  float* __restrict__ alpha,
                                  int* __restrict__ mkey, int Ntot) {
    int t = blockIdx.x * blockDim.x + threadIdx.x;
    int tot = (Ef + Er) * 8;
    if (t >= tot) return;
    int h = t & 7;
    int e = t >> 3;
    int src, dst, et;
    if (e < Ef) { et = 0; src = ef[e]; dst = ef[Ef + e]; }
    else        { int e2 = e - Ef; et = 1; src = er[e2]; dst = er[Er + e2]; }

    const float4* qp = (const float4*)(kqv + (size_t)dst * 384 + 128 + h * 16);
    const float4* kp = (const float4*)(k_rel + ((size_t)et * Ntot + src) * 128 + h * 16);
    float s = 0.f;
#pragma unroll
    for (int i = 0; i < 4; i++) {
        float4 a = qp[i], b = kp[i];
        s += a.x * b.x + a.y * b.y + a.z * b.z + a.w * b.w;
    }
    s *= p_rel_l[et * 8 + h] * 0.25f;  // scale = 1/sqrt(16)
    alpha[(size_t)e * 8 + h] = s;
    atomicMax(mkey + (size_t)dst * 8 + h, f2okey(s));
}

// ---------------- edge pass 2: exp, denom, weighted V aggregation -----------
__global__ void edge_agg_kernel(const int* __restrict__ ef, const int* __restrict__ er,
                                int Ef, int Er,
                                const float* __restrict__ v_rel,
                                const float* __restrict__ alpha,
                                const int* __restrict__ mkey,
                                float* __restrict__ denom,
                                float* __restrict__ agg, int Ntot) {
    int t = blockIdx.x * blockDim.x + threadIdx.x;
    int tot = (Ef + Er) * 8;
    if (t >= tot) return;
    int h = t & 7;
    int e = t >> 3;
    int src, dst, et;
    if (e < Ef) { et = 0; src = ef[e]; dst = ef[Ef + e]; }
    else        { int e2 = e - Ef; et = 1; src = er[e2]; dst = er[Er + e2]; }

    float m = okey2f(mkey[(size_t)dst * 8 + h]);
    float ex = expf(alpha[(size_t)e * 8 + h] - m);
    atomicAdd(denom + (size_t)dst * 8 + h, ex);

    const float4* vp = (const float4*)(v_rel + ((size_t)et * Ntot + src) * 128 + h * 16);
    float* ag = agg + (size_t)dst * 128 + h * 16;
#pragma unroll
    for (int i = 0; i < 4; i++) {
        float4 v = vp[i];
        atomicAdd(ag + i * 4 + 0, ex * v.x);
        atomicAdd(ag + i * 4 + 1, ex * v.y);
        atomicAdd(ag + i * 4 + 2, ex * v.z);
        atomicAdd(ag + i * 4 + 3, ex * v.w);
    }
}

// ---------------- normalize + exact GELU -------------------------------------
__global__ void finalize_kernel(float* __restrict__ agg, const float* __restrict__ denom,
                                int n) {
    int t = blockIdx.x * blockDim.x + threadIdx.x;
    if (t >= n * 128) return;
    int node = t >> 7;
    int h = (t >> 4) & 7;
    float v = agg[t] / (denom[node * 8 + h] + 1e-16f);
    agg[t] = 0.5f * v * (1.0f + erff(v * 0.70710678118654752440f));
}

// ---------------- head: logits [N,2] -----------------------------------------
__global__ void head_kernel(const float* __restrict__ h, const float* __restrict__ w,
                            const float* __restrict__ b, float* __restrict__ out, int n) {
    int gw = (blockIdx.x * blockDim.x + threadIdx.x) >> 5;
    int lane = threadIdx.x & 31;
    if (gw >= n) return;
    const float* hr = h + (size_t)gw * 128;
    float s0 = 0.f, s1 = 0.f;
#pragma unroll
    for (int k = lane; k < 128; k += 32) {
        float hv = hr[k];
        s0 = fmaf(hv, w[k * 2 + 0], s0);
        s1 = fmaf(hv, w[k * 2 + 1], s1);
    }
#pragma unroll
    for (int o = 16; o > 0; o >>= 1) {
        s0 += __shfl_down_sync(0xFFFFFFFFu, s0, o);
        s1 += __shfl_down_sync(0xFFFFFFFFu, s1, o);
    }
    if (lane == 0) {
        out[(size_t)gw * 2 + 0] = s0 + b[0];
        out[(size_t)gw * 2 + 1] = s1 + b[1];
    }
}

// ---------------- launch ------------------------------------------------------
extern "C" void kernel_launch(void* const* d_in, const int* in_sizes, int n_in,
                              void* d_out, int out_size) {
    const float* x       = (const float*)d_in[0];
    const int*   ef      = (const int*)d_in[1];
    const int*   er      = (const int*)d_in[2];
    const float* in_w    = (const float*)d_in[3];
    const float* in_b    = (const float*)d_in[4];
    const float* kqv_w   = (const float*)d_in[5];
    const float* kqv_b   = (const float*)d_in[6];
    const float* krel_w  = (const float*)d_in[7];
    const float* vrel_w  = (const float*)d_in[8];
    const float* p_rel   = (const float*)d_in[9];
    const float* out_w   = (const float*)d_in[10];
    const float* out_b   = (const float*)d_in[11];
    const float* skip    = (const float*)d_in[12];
    const float* head_w  = (const float*)d_in[13];
    const float* head_b  = (const float*)d_in[14];
    float* out = (float*)d_out;

    const int N  = in_sizes[0] / FF;
    const int Ef = in_sizes[1] / 2;
    const int Er = in_sizes[2] / 2;
    const int Etot = Ef + Er;

    float* hbuf;   cudaGetSymbolAddress((void**)&hbuf, g_h);
    float* kqv;    cudaGetSymbolAddress((void**)&kqv, g_kqv);
    float* krel;   cudaGetSymbolAddress((void**)&krel, g_krel);
    float* vrel;   cudaGetSymbolAddress((void**)&vrel, g_vrel);
    float* alpha;  cudaGetSymbolAddress((void**)&alpha, g_alpha);
    int*   mkey;   cudaGetSymbolAddress((void**)&mkey, g_mkey);
    float* denom;  cudaGetSymbolAddress((void**)&denom, g_denom);
    float* agg;    cudaGetSymbolAddress((void**)&agg, g_agg);

    const int gmRows = (N + 127) / 128;

    // h = x @ in_w + in_b
    gemm128_kernel<0><<<dim3(gmRows, FF / 128), 256>>>(x, in_w, in_b, hbuf, N, FF, FF,
                                                       nullptr, nullptr);

    for (int l = 0; l < LL; l++) {
        // kqv = h @ kqv_w[l] + kqv_b[l]
        gemm128_kernel<0><<<dim3(gmRows, (3 * FF) / 128), 256>>>(
            hbuf, kqv_w + (size_t)l * FF * 3 * FF, kqv_b + (size_t)l * 3 * FF,
            kqv, N, 3 * FF, FF, nullptr, nullptr);

        // relation transforms
        rel_kernel<<<(N + 15) / 16, 128>>>(kqv,
                                           krel_w + (size_t)l * 2 * HH * DD * DD,
                                           vrel_w + (size_t)l * 2 * HH * DD * DD,
                                           krel, vrel, N);

        // reset segment buffers
        init_seg_kernel<<<(N * 128 + 255) / 256, 256>>>(agg, denom, mkey, N);

        // edge pass 1: logits + segment max
        edge_alpha_kernel<<<(Etot * 8 + 255) / 256, 256>>>(
            ef, er, Ef, Er, kqv, krel, p_rel + (size_t)l * 2 * HH, alpha, mkey, N);

        // edge pass 2: exp / denom / weighted aggregation
        edge_agg_kernel<<<(Etot * 8 + 255) / 256, 256>>>(
            ef, er, Ef, Er, vrel, alpha, mkey, denom, agg, N);

        // normalize + gelu
        finalize_kernel<<<(N * 128 + 255) / 256, 256>>>(agg, denom, N);

        // h = relu(g * (gelu_agg @ out_w[l] + out_b[l]) + (1-g) * h)
        gemm128_kernel<1><<<dim3(gmRows, FF / 128), 256>>>(
            agg, out_w + (size_t)l * FF * FF, out_b + (size_t)l * FF,
            nullptr, N, FF, FF, hbuf, skip + l);
    }

    // logits
    head_kernel<<<(N * 32 + 255) / 256, 256>>>(hbuf, head_w, head_b, out, N);
}

// round 3
// speedup vs baseline: 2.1592x; 2.0414x over previous
#include <cuda_runtime.h>
#include <cuda_bf16.h>
#include <math.h>

// Problem constants (fixed by the dataset)
#define NN 50000
#define EE 400000
#define FF 128
#define HH 8
#define DD 16
#define LL 2

// ---------------- scratch (device globals; no cudaMalloc allowed) ----------
__device__ float g_h[NN * FF];            // node features [N,128]
__device__ float g_kqv[NN * 3 * FF];      // [N,384]: k|q|v
__device__ float g_krel[2 * NN * FF];     // [etype,N,128]
__device__ float g_vrel[2 * NN * FF];     // [etype,N,128]
__device__ float g_agg[NN * FF];          // aggregated messages / gelu buffer
// CSR of incoming edges (built once per launch; edges static across layers)
__device__ int g_cnt[NN];                 // degree histogram / scatter cursor
__device__ int g_rowptr[NN + 1];
__device__ int g_csr[2 * EE];             // packed: src | (etype<<24)

// ================= GEMM: C[M,Nc] = A[M,K] @ B[K,Nc] (+bias, optional skip) ==
// 128x128 tile, BK=16, 256 threads, 8x8 micro-tile, double-buffered smem,
// packed f32x2 FMA (FFMA2) in the inner loop.
#define ASTR 132

template <int EPI>
__global__ __launch_bounds__(256, 2)
void gemm128_kernel(const float* __restrict__ A,
                    const float* __restrict__ B,
                    const float* __restrict__ bias,
                    float* __restrict__ C,
                    int M, int Nc, int K,
                    float* __restrict__ hio,
                    const float* __restrict__ skip_p) {
    __shared__ float As[2][16][ASTR];   // [buf][k][row]
    __shared__ float Bs[2][16][128];    // [buf][k][col]

    const int tid = threadIdx.x;
    const int tx = tid & 15;
    const int ty = tid >> 4;
    const int rowBase = blockIdx.x * 128;
    const int colBase = blockIdx.y * 128;

    const int arow  = tid >> 2;
    const int aquad = tid & 3;
    const int brow = tid >> 5;
    const int bcol = (tid & 31) * 4;

    const int ntiles = K >> 4;

    {
        const int gr0 = rowBase + arow;
        const int gr1 = gr0 + 64;
        float4 a0 = make_float4(0.f, 0.f, 0.f, 0.f), a1 = a0;
        if (gr0 < M) a0 = *(const float4*)(A + (size_t)gr0 * K + aquad * 4);
        if (gr1 < M) a1 = *(const float4*)(A + (size_t)gr1 * K + aquad * 4);
        As[0][aquad * 4 + 0][arow] = a0.x;  As[0][aquad * 4 + 1][arow] = a0.y;
        As[0][aquad * 4 + 2][arow] = a0.z;  As[0][aquad * 4 + 3][arow] = a0.w;
        As[0][aquad * 4 + 0][arow + 64] = a1.x;  As[0][aquad * 4 + 1][arow + 64] = a1.y;
        As[0][aquad * 4 + 2][arow + 64] = a1.z;  As[0][aquad * 4 + 3][arow + 64] = a1.w;
        float4 b0 = *(const float4*)(B + (size_t)brow * Nc + colBase + bcol);
        float4 b1 = *(const float4*)(B + (size_t)(brow + 8) * Nc + colBase + bcol);
        *(float4*)&Bs[0][brow][bcol]     = b0;
        *(float4*)&Bs[0][brow + 8][bcol] = b1;
    }
    __syncthreads();

    unsigned long long acc[8][4];
#pragma unroll
    for (int i = 0; i < 8; i++)
#pragma unroll
        for (int j = 0; j < 4; j++) acc[i][j] = 0ULL;

    for (int kt = 0; kt < ntiles; kt++) {
        const int cur = kt & 1;
        const bool has = (kt + 1 < ntiles);
        float4 pa0, pa1, pb0, pb1;
        if (has) {
            const int k0 = (kt + 1) << 4;
            const int gr0 = rowBase + arow;
            const int gr1 = gr0 + 64;
            pa0 = make_float4(0.f, 0.f, 0.f, 0.f);
            pa1 = pa0;
            if (gr0 < M) pa0 = *(const float4*)(A + (size_t)gr0 * K + k0 + aquad * 4);
            if (gr1 < M) pa1 = *(const float4*)(A + (size_t)gr1 * K + k0 + aquad * 4);
            pb0 = *(const float4*)(B + (size_t)(k0 + brow) * Nc + colBase + bcol);
            pb1 = *(const float4*)(B + (size_t)(k0 + brow + 8) * Nc + colBase + bcol);
        }

#pragma unroll
        for (int kk = 0; kk < 16; kk++) {
            float4 av0 = *(const float4*)&As[cur][kk][ty * 8];
            float4 av1 = *(const float4*)&As[cur][kk][ty * 8 + 4];
            ulonglong2 bv0 = *(const ulonglong2*)&Bs[cur][kk][tx * 8];
            ulonglong2 bv1 = *(const ulonglong2*)&Bs[cur][kk][tx * 8 + 4];
            unsigned long long b2[4] = {bv0.x, bv0.y, bv1.x, bv1.y};
            float af[8] = {av0.x, av0.y, av0.z, av0.w, av1.x, av1.y, av1.z, av1.w};
#pragma unroll
            for (int i = 0; i < 8; i++) {
                unsigned long long a2;
                asm("mov.b64 %0, {%1, %1};" : "=l"(a2) : "f"(af[i]));
#pragma unroll
                for (int jp = 0; jp < 4; jp++) {
                    asm("fma.rn.f32x2 %0, %1, %2, %0;"
                        : "+l"(acc[i][jp]) : "l"(a2), "l"(b2[jp]));
                }
            }
        }

        if (has) {
            const int nxt = cur ^ 1;
            As[nxt][aquad * 4 + 0][arow] = pa0.x;  As[nxt][aquad * 4 + 1][arow] = pa0.y;
            As[nxt][aquad * 4 + 2][arow] = pa0.z;  As[nxt][aquad * 4 + 3][arow] = pa0.w;
            As[nxt][aquad * 4 + 0][arow + 64] = pa1.x;  As[nxt][aquad * 4 + 1][arow + 64] = pa1.y;
            As[nxt][aquad * 4 + 2][arow + 64] = pa1.z;  As[nxt][aquad * 4 + 3][arow + 64] = pa1.w;
            *(float4*)&Bs[nxt][brow][bcol]     = pb0;
            *(float4*)&Bs[nxt][brow + 8][bcol] = pb1;
            __syncthreads();
        }
    }

    float g = 0.0f;
    if (EPI == 1) g = 1.0f / (1.0f + expf(-skip_p[0]));

    float4 bb0 = *(const float4*)(bias + colBase + tx * 8);
    float4 bb1 = *(const float4*)(bias + colBase + tx * 8 + 4);

#pragma unroll
    for (int i = 0; i < 8; i++) {
        const int row = rowBase + ty * 8 + i;
        if (row >= M) continue;
        float c[8];
#pragma unroll
        for (int jp = 0; jp < 4; jp++) {
            asm("mov.b64 {%0, %1}, %2;"
                : "=f"(c[jp * 2]), "=f"(c[jp * 2 + 1]) : "l"(acc[i][jp]));
        }
        c[0] += bb0.x; c[1] += bb0.y; c[2] += bb0.z; c[3] += bb0.w;
        c[4] += bb1.x; c[5] += bb1.y; c[6] += bb1.z; c[7] += bb1.w;
        const size_t o = (size_t)row * Nc + colBase + tx * 8;
        if (EPI == 0) {
            *(float4*)(C + o)     = make_float4(c[0], c[1], c[2], c[3]);
            *(float4*)(C + o + 4) = make_float4(c[4], c[5], c[6], c[7]);
        } else {
            float4 h0 = *(const float4*)(hio + o);
            float4 h1 = *(const float4*)(hio + o + 4);
            float4 r0, r1;
            r0.x = fmaxf(g * c[0] + (1.0f - g) * h0.x, 0.0f);
            r0.y = fmaxf(g * c[1] + (1.0f - g) * h0.y, 0.0f);
            r0.z = fmaxf(g * c[2] + (1.0f - g) * h0.z, 0.0f);
            r0.w = fmaxf(g * c[3] + (1.0f - g) * h0.w, 0.0f);
            r1.x = fmaxf(g * c[4] + (1.0f - g) * h1.x, 0.0f);
            r1.y = fmaxf(g * c[5] + (1.0f - g) * h1.y, 0.0f);
            r1.z = fmaxf(g * c[6] + (1.0f - g) * h1.z, 0.0f);
            r1.w = fmaxf(g * c[7] + (1.0f - g) * h1.w, 0.0f);
            *(float4*)(hio + o)     = r0;
            *(float4*)(hio + o + 4) = r1;
        }
    }
}

// ---------------- relation transform: k_rel/v_rel per edge type -------------
__global__ void rel_kernel(const float* __restrict__ kqv,
                           const float* __restrict__ krel_w_l,   // [2,8,16,16]
                           const float* __restrict__ vrel_w_l,
                           float* __restrict__ k_rel,
                           float* __restrict__ v_rel,
                           int Ntot) {
    __shared__ float wk[4096];
    __shared__ float wv[4096];
    __shared__ float sk[128];
    __shared__ float sv[128];
    const int tid = threadIdx.x;  // 128
    for (int i = tid; i < 4096; i += 128) {
        wk[i] = krel_w_l[i];
        wv[i] = vrel_w_l[i];
    }
    __syncthreads();
    const int h = tid >> 4;
    const int f = tid & 15;
    const int base = blockIdx.x * 16;
    for (int nn = 0; nn < 16; nn++) {
        int n = base + nn;
        if (n >= Ntot) break;
        sk[tid] = kqv[(size_t)n * 384 + tid];
        sv[tid] = kqv[(size_t)n * 384 + 256 + tid];
        __syncthreads();
        float a0 = 0.f, a1 = 0.f, b0 = 0.f, b1 = 0.f;
#pragma unroll
        for (int d = 0; d < 16; d++) {
            float kk = sk[h * 16 + d];
            float vv = sv[h * 16 + d];
            a0 = fmaf(kk, wk[(0 * 8 + h) * 256 + d * 16 + f], a0);
            a1 = fmaf(kk, wk[(1 * 8 + h) * 256 + d * 16 + f], a1);
            b0 = fmaf(vv, wv[(0 * 8 + h) * 256 + d * 16 + f], b0);
            b1 = fmaf(vv, wv[(1 * 8 + h) * 256 + d * 16 + f], b1);
        }
        k_rel[(size_t)n * 128 + tid] = a0;
        k_rel[(size_t)Ntot * 128 + (size_t)n * 128 + tid] = a1;
        v_rel[(size_t)n * 128 + tid] = b0;
        v_rel[(size_t)Ntot * 128 + (size_t)n * 128 + tid] = b1;
        __syncthreads();
    }
}

// ================= CSR build (once per launch; edges static) ================
__global__ void zero_cnt_kernel(int* __restrict__ cnt, int n) {
    int t = blockIdx.x * blockDim.x + threadIdx.x;
    if (t < n) cnt[t] = 0;
}

__global__ void hist_kernel(const int* __restrict__ ef, const int* __restrict__ er,
                            int Ef, int Er, int* __restrict__ cnt) {
    int t = blockIdx.x * blockDim.x + threadIdx.x;
    if (t >= Ef + Er) return;
    int dst = (t < Ef) ? ef[Ef + t] : er[Er + (t - Ef)];
    atomicAdd(cnt + dst, 1);
}

// single-block exclusive scan of cnt[0..n) -> rowptr, also init cur = rowptr
__global__ void scan_kernel(const int* __restrict__ cnt, int* __restrict__ rowptr,
                            int* __restrict__ cur, int n) {
    __shared__ int buf[1024];
    __shared__ int carry;
    const int tid = threadIdx.x;
    if (tid == 0) carry = 0;
    __syncthreads();
    for (int base = 0; base < n; base += 1024) {
        int i = base + tid;
        int v = (i < n) ? cnt[i] : 0;
        buf[tid] = v;
        __syncthreads();
#pragma unroll
        for (int off = 1; off < 1024; off <<= 1) {
            int t = (tid >= off) ? buf[tid - off] : 0;
            __syncthreads();
            buf[tid] += t;
            __syncthreads();
        }
        int excl = carry + buf[tid] - v;
        if (i < n) { rowptr[i] = excl; cur[i] = excl; }
        __syncthreads();
        if (tid == 0) carry += buf[1023];
        __syncthreads();
    }
    if (tid == 0) rowptr[n] = carry;
}

__global__ void scatter_kernel(const int* __restrict__ ef, const int* __restrict__ er,
                               int Ef, int Er, int* __restrict__ cur,
                               int* __restrict__ csr) {
    int t = blockIdx.x * blockDim.x + threadIdx.x;
    if (t >= Ef + Er) return;
    int src, dst, et;
    if (t < Ef) { et = 0; src = ef[t]; dst = ef[Ef + t]; }
    else        { int e2 = t - Ef; et = 1; src = er[e2]; dst = er[Er + e2]; }
    int pos = atomicAdd(cur + dst, 1);
    csr[pos] = src | (et << 24);
}

// ========== node attention: warp per node, online softmax, fused GELU =======
// lane = h*4 + part;  part covers dims [part*4, part*4+4)
__global__ __launch_bounds__(256)
void node_attn_kernel(const int* __restrict__ rowptr, const int* __restrict__ csr,
                      const float* __restrict__ kqv,
                      const float* __restrict__ k_rel, const float* __restrict__ v_rel,
                      const float* __restrict__ p_rel_l,   // [2,8]
                      float* __restrict__ agg, int Ntot) {
    const int node = blockIdx.x * 8 + (threadIdx.x >> 5);
    if (node >= Ntot) return;
    const int lane = threadIdx.x & 31;
    const int h = lane >> 2;
    const int part = lane & 3;
    const int off = h * 16 + part * 4;

    const float4 q = *(const float4*)(kqv + (size_t)node * 384 + 128 + off);
    const float p0 = p_rel_l[h] * 0.25f;        // scale = 1/sqrt(16)
    const float p1 = p_rel_l[8 + h] * 0.25f;

    float m = -INFINITY;
    float den = 0.0f;
    float4 acc = make_float4(0.f, 0.f, 0.f, 0.f);

    const int beg = rowptr[node];
    const int end = rowptr[node + 1];
    for (int i = beg; i < end; i++) {
        const int packed = csr[i];
        const int src = packed & 0x00FFFFFF;
        const int et = packed >> 24;
        const size_t rbase = ((size_t)et * Ntot + src) * 128 + off;
        const float4 kv = *(const float4*)(k_rel + rbase);
        const float4 vv = *(const float4*)(v_rel + rbase);

        float d = q.x * kv.x + q.y * kv.y + q.z * kv.z + q.w * kv.w;
        d += __shfl_xor_sync(0xFFFFFFFFu, d, 1);
        d += __shfl_xor_sync(0xFFFFFFFFu, d, 2);
        const float alpha = d * (et ? p1 : p0);

        const float mn = fmaxf(m, alpha);
        const float scale = __expf(m - mn);     // exp(-inf)=0 on first edge
        const float ex = __expf(alpha - mn);
        den = den * scale + ex;
        acc.x = acc.x * scale + ex * vv.x;
        acc.y = acc.y * scale + ex * vv.y;
        acc.z = acc.z * scale + ex * vv.z;
        acc.w = acc.w * scale + ex * vv.w;
        m = mn;
    }

    const float inv = 1.0f / (den + 1e-16f);
    float4 r;
    const float c = 0.70710678118654752440f;
    float v0 = acc.x * inv, v1 = acc.y * inv, v2 = acc.z * inv, v3 = acc.w * inv;
    r.x = 0.5f * v0 * (1.0f + erff(v0 * c));
    r.y = 0.5f * v1 * (1.0f + erff(v1 * c));
    r.z = 0.5f * v2 * (1.0f + erff(v2 * c));
    r.w = 0.5f * v3 * (1.0f + erff(v3 * c));
    *(float4*)(agg + (size_t)node * 128 + off) = r;
}

// ---------------- head: logits [N,2] -----------------------------------------
__global__ void head_kernel(const float* __restrict__ h, const float* __restrict__ w,
                            const float* __restrict__ b, float* __restrict__ out, int n) {
    int gw = (blockIdx.x * blockDim.x + threadIdx.x) >> 5;
    int lane = threadIdx.x & 31;
    if (gw >= n) return;
    const float* hr = h + (size_t)gw * 128;
    float s0 = 0.f, s1 = 0.f;
#pragma unroll
    for (int k = lane; k < 128; k += 32) {
        float hv = hr[k];
        s0 = fmaf(hv, w[k * 2 + 0], s0);
        s1 = fmaf(hv, w[k * 2 + 1], s1);
    }
#pragma unroll
    for (int o = 16; o > 0; o >>= 1) {
        s0 += __shfl_down_sync(0xFFFFFFFFu, s0, o);
        s1 += __shfl_down_sync(0xFFFFFFFFu, s1, o);
    }
    if (lane == 0) {
        out[(size_t)gw * 2 + 0] = s0 + b[0];
        out[(size_t)gw * 2 + 1] = s1 + b[1];
    }
}

// ---------------- launch ------------------------------------------------------
extern "C" void kernel_launch(void* const* d_in, const int* in_sizes, int n_in,
                              void* d_out, int out_size) {
    const float* x       = (const float*)d_in[0];
    const int*   ef      = (const int*)d_in[1];
    const int*   er      = (const int*)d_in[2];
    const float* in_w    = (const float*)d_in[3];
    const float* in_b    = (const float*)d_in[4];
    const float* kqv_w   = (const float*)d_in[5];
    const float* kqv_b   = (const float*)d_in[6];
    const float* krel_w  = (const float*)d_in[7];
    const float* vrel_w  = (const float*)d_in[8];
    const float* p_rel   = (const float*)d_in[9];
    const float* out_w   = (const float*)d_in[10];
    const float* out_b   = (const float*)d_in[11];
    const float* skip    = (const float*)d_in[12];
    const float* head_w  = (const float*)d_in[13];
    const float* head_b  = (const float*)d_in[14];
    float* out = (float*)d_out;

    const int N  = in_sizes[0] / FF;
    const int Ef = in_sizes[1] / 2;
    const int Er = in_sizes[2] / 2;
    const int Etot = Ef + Er;

    float* hbuf;   cudaGetSymbolAddress((void**)&hbuf, g_h);
    float* kqv;    cudaGetSymbolAddress((void**)&kqv, g_kqv);
    float* krel;   cudaGetSymbolAddress((void**)&krel, g_krel);
    float* vrel;   cudaGetSymbolAddress((void**)&vrel, g_vrel);
    float* agg;    cudaGetSymbolAddress((void**)&agg, g_agg);
    int* cnt;      cudaGetSymbolAddress((void**)&cnt, g_cnt);
    int* rowptr;   cudaGetSymbolAddress((void**)&rowptr, g_rowptr);
    int* csr;      cudaGetSymbolAddress((void**)&csr, g_csr);

    const int gmRows = (N + 127) / 128;

    // ---- CSR of incoming edges (dst-major), built once, reused both layers
    zero_cnt_kernel<<<(N + 255) / 256, 256>>>(cnt, N);
    hist_kernel<<<(Etot + 255) / 256, 256>>>(ef, er, Ef, Er, cnt);
    scan_kernel<<<1, 1024>>>(cnt, rowptr, cnt, N);   // cnt becomes scatter cursor
    scatter_kernel<<<(Etot + 255) / 256, 256>>>(ef, er, Ef, Er, cnt, csr);

    // h = x @ in_w + in_b
    gemm128_kernel<0><<<dim3(gmRows, FF / 128), 256>>>(x, in_w, in_b, hbuf, N, FF, FF,
                                                       nullptr, nullptr);

    for (int l = 0; l < LL; l++) {
        // kqv = h @ kqv_w[l] + kqv_b[l]
        gemm128_kernel<0><<<dim3(gmRows, (3 * FF) / 128), 256>>>(
            hbuf, kqv_w + (size_t)l * FF * 3 * FF, kqv_b + (size_t)l * 3 * FF,
            kqv, N, 3 * FF, FF, nullptr, nullptr);

        // relation transforms
        rel_kernel<<<(N + 15) / 16, 128>>>(kqv,
                                           krel_w + (size_t)l * 2 * HH * DD * DD,
                                           vrel_w + (size_t)l * 2 * HH * DD * DD,
                                           krel, vrel, N);

        // fused attention: online softmax + aggregation + GELU (no atomics)
        node_attn_kernel<<<(N + 7) / 8, 256>>>(rowptr, csr, kqv, krel, vrel,
                                               p_rel + (size_t)l * 2 * HH, agg, N);

        // h = relu(g * (gelu_agg @ out_w[l] + out_b[l]) + (1-g) * h)
        gemm128_kernel<1><<<dim3(gmRows, FF / 128), 256>>>(
            agg, out_w + (size_t)l * FF * FF, out_b + (size_t)l * FF,
            nullptr, N, FF, FF, hbuf, skip + l);
    }

    // logits
    head_kernel<<<(N * 32 + 255) / 256, 256>>>(hbuf, head_w, head_b, out, N);
}